// round 10
// baseline (speedup 1.0000x reference)
#include <cuda_runtime.h>
#include <cuda_bf16.h>
#include <cstdint>

// B=32 images of 512x512 fp32 (output, density_map), 3 int64 bboxes/batch.
// R10: few long streams (validated R9) + register-free in-flight via
// cp.async.bulk deep pipeline. Grid 128 = 1 CTA/SM single wave; each block
// streams a contiguous 256KB per array through a 4-stage x 16KB smem pipeline
// (up to 96KB outstanding per block, ~12MB chip-wide). Compute from LDS.
// Last-block fused finalize kept.

#define IMG_H 512
#define IMG_W 512
#define HW (IMG_H * IMG_W)        // 262144 floats per image
#define NBATCH 32
#define NBOX 3
#define BPB 4                     // blocks per batch
#define NB (NBATCH * BPB)         // 128 blocks
#define SPAN 65536                // floats per array per block (256KB)
#define STAGE 4096                // floats per array per stage (16KB)
#define NSTAGE (SPAN / STAGE)     // 16
#define DEPTH 4                   // pipeline stages
#define STAGE_BYTES (STAGE * 4)   // 16384
#define SMEM_BYTES (2 * DEPTH * STAGE_BYTES)   // 128KB dynamic

__device__ float g_sq[NB];
__device__ float g_bd[NB];
__device__ float g_box[NBOX][NB];
__device__ unsigned int g_count;  // zero-init at load; reset by last block

__device__ __forceinline__ uint32_t smem_u32(const void* p) {
    return (uint32_t)__cvta_generic_to_shared(p);
}
__device__ __forceinline__ void mbar_init(uint32_t a, uint32_t n) {
    asm volatile("mbarrier.init.shared.b64 [%0], %1;" :: "r"(a), "r"(n) : "memory");
}
__device__ __forceinline__ void mbar_expect_tx(uint32_t a, uint32_t bytes) {
    asm volatile("mbarrier.arrive.expect_tx.shared.b64 _, [%0], %1;"
                 :: "r"(a), "r"(bytes) : "memory");
}
__device__ __forceinline__ void bulk_g2s(uint32_t dst, const void* src,
                                         uint32_t bytes, uint32_t mbar) {
    asm volatile(
        "cp.async.bulk.shared::cta.global.mbarrier::complete_tx::bytes "
        "[%0], [%1], %2, [%3];"
        :: "r"(dst), "l"(src), "r"(bytes), "r"(mbar) : "memory");
}
__device__ __forceinline__ void mbar_wait(uint32_t a, uint32_t phase) {
    uint32_t done;
    do {
        asm volatile(
            "{\n\t.reg .pred p;\n\t"
            "mbarrier.try_wait.parity.shared.b64 p, [%1], %2, 0x989680;\n\t"
            "selp.b32 %0, 1, 0, p;\n\t}"
            : "=r"(done) : "r"(a), "r"(phase) : "memory");
    } while (!done);
}

__global__ __launch_bounds__(256, 1)
void crit_kernel(const float* __restrict__ out_p,
                 const float* __restrict__ dmp_p,
                 const long long* __restrict__ bbox_p,
                 float* __restrict__ out3,
                 const unsigned char* __restrict__ nobj_ptr)
{
    const int bid = blockIdx.x;
    const int b   = bid >> 2;     // batch
    const int e   = bid & 3;      // quarter within batch
    const int t   = threadIdx.x;
    const int wid = t >> 5, lid = t & 31;

    extern __shared__ __align__(128) float dyn[];
    float* so = dyn;                       // [DEPTH][STAGE]
    float* sd = dyn + DEPTH * STAGE;       // [DEPTH][STAGE]

    __shared__ __align__(8) unsigned long long barmem[DEPTH];
    __shared__ int sbb[NBOX * 4];

    uint32_t barA[DEPTH], soA[DEPTH], sdA[DEPTH];
#pragma unroll
    for (int k = 0; k < DEPTH; k++) {
        barA[k] = smem_u32(&barmem[k]);
        soA[k]  = smem_u32(so + k * STAGE);
        sdA[k]  = smem_u32(sd + k * STAGE);
    }

    // Load + clip this batch's 3 bboxes into shared
    if (t < NBOX * 4) {
        long long v = bbox_p[(size_t)b * NBOX * 4 + t];
        if (v < 0) v = 0;
        if (v > IMG_W) v = IMG_W;
        sbb[t] = (int)v;
    }
    if (t == 0) {
#pragma unroll
        for (int k = 0; k < DEPTH; k++) mbar_init(barA[k], 1);
    }
    __syncthreads();

    int bx1[NBOX], by1[NBOX], bx2[NBOX], by2[NBOX];
#pragma unroll
    for (int j = 0; j < NBOX; j++) {
        bx1[j] = sbb[j * 4 + 0];
        by1[j] = sbb[j * 4 + 1];
        bx2[j] = max(sbb[j * 4 + 2], bx1[j]);
        by2[j] = max(sbb[j * 4 + 3], by1[j]);
    }

    const float* gso = out_p + (size_t)b * HW + (size_t)e * SPAN;
    const float* gsd = dmp_p + (size_t)b * HW + (size_t)e * SPAN;

    // Prologue: fill all DEPTH stages
    if (t == 0) {
#pragma unroll
        for (int k = 0; k < DEPTH; k++) {
            mbar_expect_tx(barA[k], 2 * STAGE_BYTES);
            bulk_g2s(soA[k], gso + k * STAGE, STAGE_BYTES, barA[k]);
            bulk_g2s(sdA[k], gsd + k * STAGE, STAGE_BYTES, barA[k]);
        }
    }

    float sq = 0.f, bd = 0.f;
    float bs[NBOX] = {0.f, 0.f, 0.f};

    for (int s = 0; s < NSTAGE; s++) {
        const int buf = s & (DEPTH - 1);
        const int ph  = (s / DEPTH) & 1;
        mbar_wait(barA[buf], ph);

        const float4* ob = (const float4*)(so + buf * STAGE);
        const float4* db = (const float4*)(sd + buf * STAGE);

#pragma unroll
        for (int k = 0; k < STAGE / 1024; k++) {    // 4 float4 per thread
            int i4  = t + k * 256;                  // float4 idx within stage
            float4 o = ob[i4];
            float4 d = db[i4];
            float dx = o.x - d.x, dy = o.y - d.y, dz = o.z - d.z, dw = o.w - d.w;
            sq += dx * dx + dy * dy + dz * dz + dw * dw;
            bd += (dx + dy) + (dz + dw);

            int pix = (e * (SPAN / 4) + s * 1024 + i4) << 2;  // element index
            int y   = pix >> 9;
            int x0  = pix & 511;
#pragma unroll
            for (int j = 0; j < NBOX; j++) {
                if (y >= by1[j] && y < by2[j]) {
                    float ssum = 0.f;
                    if (x0     >= bx1[j] && x0     < bx2[j]) ssum += o.x;
                    if (x0 + 1 >= bx1[j] && x0 + 1 < bx2[j]) ssum += o.y;
                    if (x0 + 2 >= bx1[j] && x0 + 2 < bx2[j]) ssum += o.z;
                    if (x0 + 3 >= bx1[j] && x0 + 3 < bx2[j]) ssum += o.w;
                    bs[j] += ssum;
                }
            }
        }

        __syncthreads();   // all reads of buf done before refill
        if (t == 0 && s + DEPTH < NSTAGE) {
            mbar_expect_tx(barA[buf], 2 * STAGE_BYTES);
            bulk_g2s(soA[buf], gso + (s + DEPTH) * STAGE, STAGE_BYTES, barA[buf]);
            bulk_g2s(sdA[buf], gsd + (s + DEPTH) * STAGE, STAGE_BYTES, barA[buf]);
        }
    }

    // Block reduce 5 floats: warp shuffle, then across 8 warps via shared.
    float v5[5] = {sq, bd, bs[0], bs[1], bs[2]};
#pragma unroll
    for (int k = 0; k < 5; k++) {
#pragma unroll
        for (int off = 16; off > 0; off >>= 1)
            v5[k] += __shfl_xor_sync(0xFFFFFFFFu, v5[k], off);
    }
    __shared__ float wsum[8][5];
    if (lid == 0) {
#pragma unroll
        for (int k = 0; k < 5; k++) wsum[wid][k] = v5[k];
    }
    __syncthreads();

    __shared__ bool isLast;
    if (t == 0) {
        float a0 = 0, a1 = 0, a2 = 0, a3 = 0, a4 = 0;
#pragma unroll
        for (int w = 0; w < 8; w++) {
            a0 += wsum[w][0]; a1 += wsum[w][1]; a2 += wsum[w][2];
            a3 += wsum[w][3]; a4 += wsum[w][4];
        }
        g_sq[bid]     = a0;
        g_bd[bid]     = a1;
        g_box[0][bid] = a2;
        g_box[1][bid] = a3;
        g_box[2][bid] = a4;
        __threadfence();
        unsigned int old = atomicAdd(&g_count, 1u);
        isLast = (old == NB - 1);
    }
    __syncthreads();
    if (!isLast) return;

    // ---------- last-block finalization (128 partials, L2-hot) ----------
    __shared__ double shd[256];
    __shared__ double sh_out[4];   // [0]=count_sum, [1..3]=box margins

    shd[t] = (t < NB) ? (double)__ldcg(&g_sq[t]) : 0.0;
    __syncthreads();
#pragma unroll
    for (int o = 128; o > 0; o >>= 1) {
        if (t < o) shd[t] += shd[t + o];
        __syncthreads();
    }
    double total_sq = shd[0];

    // warp 0: count loss. lane = batch, sum its 4 bd partials (fixed order).
    if (wid == 0) {
        double v = 0.0;
#pragma unroll
        for (int k = 0; k < BPB; k++)
            v += (double)__ldcg(&g_bd[lid * BPB + k]);
        double c = v * v;
#pragma unroll
        for (int off = 16; off > 0; off >>= 1)
            c += __shfl_xor_sync(0xFFFFFFFFu, c, off);
        if (lid == 0) sh_out[0] = c;
    }
    // warps 1-3: box j margin sums. lane = batch.
    if (wid >= 1 && wid <= 3) {
        int j = wid - 1;
        double v = 0.0;
#pragma unroll
        for (int k = 0; k < BPB; k++)
            v += (double)__ldcg(&g_box[j][lid * BPB + k]);
        double r = 1.0 - v;
        double m = (r > 0.0) ? r : 0.0;
#pragma unroll
        for (int off = 16; off > 0; off >>= 1)
            m += __shfl_xor_sync(0xFFFFFFFFu, m, off);
        if (lid == 0) sh_out[wid] = m;
    }
    __syncthreads();

    if (t == 0) {
        // Decode num_objects robustly (int32/int64 LE, or fp32).
        double num = 96.0;
        if (nobj_ptr) {
            int iv;
            memcpy(&iv, nobj_ptr, sizeof(int));
            if (iv > 0 && iv < (1 << 26)) {
                num = (double)iv;
            } else {
                float fv = __int_as_float(iv);
                if (fv > 0.5f && fv < 1e8f) num = (double)fv;
            }
        }
        out3[0] = (float)(total_sq / num);
        out3[1] = (float)(sh_out[0] / (double)NBATCH);
        out3[2] = (float)(sh_out[1] + sh_out[2] + sh_out[3]);
        g_count = 0;   // reset for next graph replay
    }
}

extern "C" void kernel_launch(void* const* d_in, const int* in_sizes, int n_in,
                              void* d_out, int out_size)
{
    const float*     out_p  = (const float*)d_in[0];
    const float*     dmp_p  = (const float*)d_in[1];
    const long long* bbox_p = (const long long*)d_in[2];
    const unsigned char* nobj = (n_in > 3) ? (const unsigned char*)d_in[3] : nullptr;
    (void)in_sizes; (void)out_size;

    cudaFuncSetAttribute(crit_kernel,
                         cudaFuncAttributeMaxDynamicSharedMemorySize, SMEM_BYTES);
    crit_kernel<<<NB, 256, SMEM_BYTES>>>(out_p, dmp_p, bbox_p, (float*)d_out, nobj);
}